// round 3
// baseline (speedup 1.0000x reference)
#include <cuda_runtime.h>
#include <cstdint>

#define NB 32
#define NT 1024
#define ND 512
#define NU 512

// 64MB scratch for xw = x @ kernel   (static __device__ — no allocation)
__device__ float g_xw[NB * NT * NU];

// ---------------- f32x2 packed helpers ----------------
__device__ __forceinline__ unsigned long long pk2(float x, float y) {
    unsigned long long r;
    asm("mov.b64 %0, {%1, %2};" : "=l"(r) : "f"(x), "f"(y));
    return r;
}
__device__ __forceinline__ unsigned long long pk2s(float x) {
    unsigned long long r;
    asm("mov.b64 %0, {%1, %1};" : "=l"(r) : "f"(x));
    return r;
}
__device__ __forceinline__ void fma2(unsigned long long& d, unsigned long long a,
                                     unsigned long long b) {
    asm("fma.rn.f32x2 %0, %1, %2, %0;" : "+l"(d) : "l"(a), "l"(b));
}
__device__ __forceinline__ float2 upk2(unsigned long long a) {
    float2 r;
    asm("mov.b64 {%0, %1}, %2;" : "=f"(r.x), "=f"(r.y) : "l"(a));
    return r;
}

// ======================================================================
// Kernel 1: XW = X[32768,512] @ W[512,512], fp32, f32x2-packed SIMT GEMM
// ======================================================================
__global__ __launch_bounds__(256) void xw_gemm(const float* __restrict__ X,
                                               const float* __restrict__ W) {
    __shared__ float As[8][128];
    __shared__ float Bs[8][128];

    const int tid = threadIdx.x;
    const int m0 = blockIdx.y * 128;
    const int n0 = blockIdx.x * 128;

    const int ar = tid >> 1;
    const int ac = (tid & 1) * 4;
    const int br = tid >> 5;
    const int bc = (tid & 31) * 4;

    const int tx = tid & 15;
    const int ty = tid >> 4;

    unsigned long long acc[8][4];
#pragma unroll
    for (int i = 0; i < 8; i++)
#pragma unroll
        for (int j = 0; j < 4; j++) acc[i][j] = 0ull;

    float4 xa = *reinterpret_cast<const float4*>(&X[(size_t)(m0 + ar) * ND + ac]);
    float4 wb = *reinterpret_cast<const float4*>(&W[(size_t)br * NU + n0 + bc]);

    const int KT = ND / 8;
    for (int kt = 0; kt < KT; kt++) {
        As[ac + 0][ar] = xa.x;
        As[ac + 1][ar] = xa.y;
        As[ac + 2][ar] = xa.z;
        As[ac + 3][ar] = xa.w;
        *reinterpret_cast<float4*>(&Bs[br][bc]) = wb;
        __syncthreads();

        if (kt + 1 < KT) {
            xa = *reinterpret_cast<const float4*>(
                &X[(size_t)(m0 + ar) * ND + (kt + 1) * 8 + ac]);
            wb = *reinterpret_cast<const float4*>(
                &W[(size_t)((kt + 1) * 8 + br) * NU + n0 + bc]);
        }

#pragma unroll
        for (int k = 0; k < 8; k++) {
            float4 a0 = *reinterpret_cast<const float4*>(&As[k][ty * 8]);
            float4 a1 = *reinterpret_cast<const float4*>(&As[k][ty * 8 + 4]);
            ulonglong2 bq0 = *reinterpret_cast<const ulonglong2*>(&Bs[k][tx * 8]);
            ulonglong2 bq1 = *reinterpret_cast<const ulonglong2*>(&Bs[k][tx * 8 + 4]);
            unsigned long long bb0 = bq0.x, bb1 = bq0.y, bb2 = bq1.x, bb3 = bq1.y;
            float av[8] = {a0.x, a0.y, a0.z, a0.w, a1.x, a1.y, a1.z, a1.w};
#pragma unroll
            for (int i = 0; i < 8; i++) {
                unsigned long long aa = pk2s(av[i]);
                fma2(acc[i][0], aa, bb0);
                fma2(acc[i][1], aa, bb1);
                fma2(acc[i][2], aa, bb2);
                fma2(acc[i][3], aa, bb3);
            }
        }
        __syncthreads();
    }

#pragma unroll
    for (int i = 0; i < 8; i++) {
        size_t row = (size_t)(m0 + ty * 8 + i);
        float2* op = reinterpret_cast<float2*>(&g_xw[row * NU + n0 + tx * 8]);
        op[0] = upk2(acc[i][0]);
        op[1] = upk2(acc[i][1]);
        op[2] = upk2(acc[i][2]);
        op[3] = upk2(acc[i][3]);
    }
}

// ======================================================================
// Kernel 2: sequential scan  h_t = xw_t + h_{t-1} @ R
// 16 clusters x 8 CTAs. Per-step sync via dual mbarriers + st.async.
// CRITICAL lifetime rule: no st.async at the final step (nothing consumes
// h_NT), so no async remote op can target an exiting CTA; plus one final
// cluster barrier before exit.
// ======================================================================
__global__ __launch_bounds__(256, 1) __cluster_dims__(8, 1, 1)
void scan_kernel(const float* __restrict__ R, float* __restrict__ out) {
    __shared__ float hbuf[2][2][NU];          // [parity][batch][k]   8KB
    __shared__ float red[16][2][4][16];       // [kb][b][j][q]        8KB
    __shared__ alignas(8) unsigned long long mbar[2];

    const int tid = threadIdx.x;
    uint32_t rank;
    asm("mov.u32 %0, %%cluster_ctarank;" : "=r"(rank));
    const int cluster = blockIdx.x >> 3;
    const int b0 = cluster * 2;
    const int useg = (int)rank * 64;

    const int q = tid & 15;                   // u-quad (16 quads = 64 units)
    const int kb = tid >> 4;                  // k block (16 blocks of 32)
    const int ug = useg + q * 4;
    const int k0 = kb * 32;

    // R slice as k-pairs: Rp[j][i] = {R[k0+2i][ug+j], R[k0+2i+1][ug+j]}
    unsigned long long Rp[4][16];
#pragma unroll
    for (int i = 0; i < 16; i++) {
        float4 v0 = *reinterpret_cast<const float4*>(&R[(size_t)(k0 + 2 * i) * NU + ug]);
        float4 v1 = *reinterpret_cast<const float4*>(&R[(size_t)(k0 + 2 * i + 1) * NU + ug]);
        Rp[0][i] = pk2(v0.x, v1.x);
        Rp[1][i] = pk2(v0.y, v1.y);
        Rp[2][i] = pk2(v0.z, v1.z);
        Rp[3][i] = pk2(v0.w, v1.w);
    }

    // zero h_0 buffers
    for (int i = tid; i < 4 * NU; i += 256) (&hbuf[0][0][0])[i] = 0.f;

    const uint32_t barL0 = (uint32_t)__cvta_generic_to_shared(&mbar[0]);
    const uint32_t barL1 = (uint32_t)__cvta_generic_to_shared(&mbar[1]);
    if (tid == 0) {
        asm volatile("mbarrier.init.shared.b64 [%0], 1;" :: "r"(barL0) : "memory");
        asm volatile("mbarrier.init.shared.b64 [%0], 1;" :: "r"(barL1) : "memory");
        // arm phase 0 of both barriers (bar1 <- step-1 data, bar0 <- step-2 data)
        asm volatile("mbarrier.arrive.expect_tx.shared.b64 _, [%0], %1;"
                     :: "r"(barL0), "r"(4096) : "memory");
        asm volatile("mbarrier.arrive.expect_tx.shared.b64 _, [%0], %1;"
                     :: "r"(barL1), "r"(4096) : "memory");
    }
    __syncthreads();
    // one-time cluster rendezvous: all inits/arms visible before any st.async
    asm volatile("barrier.cluster.arrive.aligned;" ::: "memory");
    asm volatile("barrier.cluster.wait.aligned;" ::: "memory");

    // owner threads (tid<128): one (batch, unit) output each
    const bool owner = tid < 128;
    const int ob = tid >> 6;
    const int ou = tid & 63;
    const int oq = ou >> 2, oj = ou & 3;
    const float* xwp = &g_xw[((size_t)(b0 + ob) * NT) * NU + useg + ou];
    float* outp = &out[((size_t)(b0 + ob) * NT) * NU + useg + ou];
    float xw_cur = owner ? xwp[0] : 0.f;

    // remote element addresses (per parity, per dest CTA) + barrier deltas
    uint32_t raddr[2][8];
    int bardelta[2];
    if (owner) {
#pragma unroll
        for (int par = 0; par < 2; par++) {
            uint32_t la = (uint32_t)__cvta_generic_to_shared(&hbuf[par][ob][useg + ou]);
            bardelta[par] = (int)((par ? barL1 : barL0) - la);
#pragma unroll
            for (int d = 0; d < 8; d++) {
                asm("mapa.shared::cluster.u32 %0, %1, %2;"
                    : "=r"(raddr[par][d]) : "r"(la), "r"(d));
            }
        }
    }

    uint32_t barAddr[2] = {barL0, barL1};
    int par[2] = {0, 0};

    for (int t = 0; t < NT; t++) {
        const int cur = t & 1;

        if (t > 0) {
            const int bsel = cur;  // data(t) tracked by mbar[t&1]
            const uint32_t ba = barAddr[bsel];
            const uint32_t ph = (uint32_t)par[bsel];
            uint32_t done;
            asm volatile(
                "{\n\t.reg .pred p;\n\t"
                "mbarrier.try_wait.parity.acquire.cluster.shared::cta.b64 p, [%1], %2;\n\t"
                "selp.b32 %0, 1, 0, p;\n\t}"
                : "=r"(done) : "r"(ba), "r"(ph) : "memory");
            while (!done) {
                asm volatile(
                    "{\n\t.reg .pred p;\n\t"
                    "mbarrier.try_wait.parity.acquire.cluster.shared::cta.b64 p, [%1], %2, 0x989680;\n\t"
                    "selp.b32 %0, 1, 0, p;\n\t}"
                    : "=r"(done) : "r"(ba), "r"(ph) : "memory");
            }
            par[bsel] ^= 1;
            // re-arm this barrier for step t+2: safe — every peer's step-(t+1)
            // wait needs tid0's step-t sends, which follow this in program order
            if (tid == 0 && (t + 2) < NT) {
                asm volatile("mbarrier.arrive.expect_tx.shared.b64 _, [%0], %1;"
                             :: "r"(ba), "r"(4096) : "memory");
            }
        }

        // prefetch next xw (hidden under FMA loop)
        float xw_nxt = 0.f;
        if (owner && (t + 1) < NT) xw_nxt = xwp[(size_t)(t + 1) * NU];

        // ---- partial matvec over this thread's 32-k block, k-paired ----
        const float* h0 = &hbuf[cur][0][k0];
        const float* h1 = &hbuf[cur][1][k0];
        unsigned long long acc[2][4][2];
#pragma unroll
        for (int b = 0; b < 2; b++)
#pragma unroll
            for (int j = 0; j < 4; j++) { acc[b][j][0] = 0ull; acc[b][j][1] = 0ull; }

#pragma unroll
        for (int g = 0; g < 8; g++) {          // 8 groups of 4 k (= 2 k-pairs)
            ulonglong2 hp0 = *reinterpret_cast<const ulonglong2*>(&h0[g * 4]);
            ulonglong2 hp1 = *reinterpret_cast<const ulonglong2*>(&h1[g * 4]);
#pragma unroll
            for (int j = 0; j < 4; j++) {
                fma2(acc[0][j][0], Rp[j][2 * g + 0], hp0.x);
                fma2(acc[0][j][1], Rp[j][2 * g + 1], hp0.y);
                fma2(acc[1][j][0], Rp[j][2 * g + 0], hp1.x);
                fma2(acc[1][j][1], Rp[j][2 * g + 1], hp1.y);
            }
        }

        // ---- stash partials: horizontal-add pairs, conflict-free layout ----
#pragma unroll
        for (int b = 0; b < 2; b++)
#pragma unroll
            for (int j = 0; j < 4; j++) {
                float2 s0 = upk2(acc[b][j][0]);
                float2 s1 = upk2(acc[b][j][1]);
                red[kb][b][j][q] = (s0.x + s0.y) + (s1.x + s1.y);
            }
        __syncthreads();

        if (owner) {
            float s = 0.f;
#pragma unroll
            for (int r8 = 0; r8 < 16; r8++) s += red[r8][ob][oj][oq];
            const float val = xw_cur + s;
            outp[(size_t)t * NU] = val;
            // push h element to all 8 cluster CTAs' next-parity buffer —
            // but NEVER at the last step (no consumer; in-flight async remote
            // stores at cluster teardown are illegal and crash the launch)
            if (t + 1 < NT) {
                const int p = cur ^ 1;
                const uint32_t v = __float_as_uint(val);
                const int bd = bardelta[p];
#pragma unroll
                for (int d = 0; d < 8; d++) {
                    const uint32_t ra = raddr[p][d];
                    const uint32_t rb = ra + bd;
                    asm volatile(
                        "st.async.shared::cluster.mbarrier::complete_tx::bytes.b32 [%0], %1, [%2];"
                        :: "r"(ra), "r"(v), "r"(rb) : "memory");
                }
            }
        }
        xw_cur = xw_nxt;
    }

    // final rendezvous: no CTA exits while peers could still touch its smem
    asm volatile("barrier.cluster.arrive.aligned;" ::: "memory");
    asm volatile("barrier.cluster.wait.aligned;" ::: "memory");
}

// ======================================================================
extern "C" void kernel_launch(void* const* d_in, const int* in_sizes, int n_in,
                              void* d_out, int out_size) {
    const float* x = (const float*)d_in[0];            // [32,1024,512]
    const float* W = (const float*)d_in[1];            // kernel [512,512]
    const float* R = (const float*)d_in[2];            // recurrent_kernel [512,512]
    float* out = (float*)d_out;                        // [32,1024,512]

    dim3 gg(NU / 128, (NB * NT) / 128);                // (4, 256)
    xw_gemm<<<gg, 256>>>(x, W);
    scan_kernel<<<128, 256>>>(R, out);                 // 16 clusters x 8 CTAs
}

// round 4
// speedup vs baseline: 1.3472x; 1.3472x over previous
#include <cuda_runtime.h>
#include <cstdint>

#define NB 32
#define NT 1024
#define ND 512
#define NU 512

// 64MB scratch for xw = x @ kernel   (static __device__ — no allocation)
__device__ float g_xw[NB * NT * NU];

// ---------------- f32x2 packed helpers ----------------
__device__ __forceinline__ unsigned long long pk2(float x, float y) {
    unsigned long long r;
    asm("mov.b64 %0, {%1, %2};" : "=l"(r) : "f"(x), "f"(y));
    return r;
}
__device__ __forceinline__ unsigned long long pk2s(float x) {
    unsigned long long r;
    asm("mov.b64 %0, {%1, %1};" : "=l"(r) : "f"(x));
    return r;
}
__device__ __forceinline__ void fma2(unsigned long long& d, unsigned long long a,
                                     unsigned long long b) {
    asm("fma.rn.f32x2 %0, %1, %2, %0;" : "+l"(d) : "l"(a), "l"(b));
}
__device__ __forceinline__ float2 upk2(unsigned long long a) {
    float2 r;
    asm("mov.b64 {%0, %1}, %2;" : "=f"(r.x), "=f"(r.y) : "l"(a));
    return r;
}

// ======================================================================
// Kernel 1: XW = X[32768,512] @ W[512,512], fp32, f32x2-packed SIMT GEMM
// ======================================================================
__global__ __launch_bounds__(256) void xw_gemm(const float* __restrict__ X,
                                               const float* __restrict__ W) {
    __shared__ float As[8][128];
    __shared__ float Bs[8][128];

    const int tid = threadIdx.x;
    const int m0 = blockIdx.y * 128;
    const int n0 = blockIdx.x * 128;

    const int ar = tid >> 1;
    const int ac = (tid & 1) * 4;
    const int br = tid >> 5;
    const int bc = (tid & 31) * 4;

    const int tx = tid & 15;
    const int ty = tid >> 4;

    unsigned long long acc[8][4];
#pragma unroll
    for (int i = 0; i < 8; i++)
#pragma unroll
        for (int j = 0; j < 4; j++) acc[i][j] = 0ull;

    float4 xa = *reinterpret_cast<const float4*>(&X[(size_t)(m0 + ar) * ND + ac]);
    float4 wb = *reinterpret_cast<const float4*>(&W[(size_t)br * NU + n0 + bc]);

    const int KT = ND / 8;
    for (int kt = 0; kt < KT; kt++) {
        As[ac + 0][ar] = xa.x;
        As[ac + 1][ar] = xa.y;
        As[ac + 2][ar] = xa.z;
        As[ac + 3][ar] = xa.w;
        *reinterpret_cast<float4*>(&Bs[br][bc]) = wb;
        __syncthreads();

        if (kt + 1 < KT) {
            xa = *reinterpret_cast<const float4*>(
                &X[(size_t)(m0 + ar) * ND + (kt + 1) * 8 + ac]);
            wb = *reinterpret_cast<const float4*>(
                &W[(size_t)((kt + 1) * 8 + br) * NU + n0 + bc]);
        }

#pragma unroll
        for (int k = 0; k < 8; k++) {
            float4 a0 = *reinterpret_cast<const float4*>(&As[k][ty * 8]);
            float4 a1 = *reinterpret_cast<const float4*>(&As[k][ty * 8 + 4]);
            ulonglong2 bq0 = *reinterpret_cast<const ulonglong2*>(&Bs[k][tx * 8]);
            ulonglong2 bq1 = *reinterpret_cast<const ulonglong2*>(&Bs[k][tx * 8 + 4]);
            unsigned long long bb0 = bq0.x, bb1 = bq0.y, bb2 = bq1.x, bb3 = bq1.y;
            float av[8] = {a0.x, a0.y, a0.z, a0.w, a1.x, a1.y, a1.z, a1.w};
#pragma unroll
            for (int i = 0; i < 8; i++) {
                unsigned long long aa = pk2s(av[i]);
                fma2(acc[i][0], aa, bb0);
                fma2(acc[i][1], aa, bb1);
                fma2(acc[i][2], aa, bb2);
                fma2(acc[i][3], aa, bb3);
            }
        }
        __syncthreads();
    }

#pragma unroll
    for (int i = 0; i < 8; i++) {
        size_t row = (size_t)(m0 + ty * 8 + i);
        float2* op = reinterpret_cast<float2*>(&g_xw[row * NU + n0 + tx * 8]);
        op[0] = upk2(acc[i][0]);
        op[1] = upk2(acc[i][1]);
        op[2] = upk2(acc[i][2]);
        op[3] = upk2(acc[i][3]);
    }
}

// ======================================================================
// Kernel 2: sequential scan  h_t = xw_t + h_{t-1} @ R
// 16 clusters x 8 CTAs. Dual mbarriers; per-step comm via 8 aggregated
// DSMEM bulk copies (cp.async.bulk S2S cluster) -> 8 tx per barrier per
// step instead of 1024 fine-grained st.async tx (R3's regression cause).
// ======================================================================
__global__ __launch_bounds__(256, 1) __cluster_dims__(8, 1, 1)
void scan_kernel(const float* __restrict__ R, float* __restrict__ out) {
    __shared__ alignas(16) float hbuf[2][8][2][64];   // [parity][srcRank][batch][unit] 4KB
    __shared__ alignas(16) float stage[2][2][64];     // [parity][batch][unit]          1KB
    __shared__ float red[16][2][4][16];               // [kb][b][j][q]                  8KB
    __shared__ alignas(8) unsigned long long mbar[2];

    const int tid = threadIdx.x;
    uint32_t rank;
    asm("mov.u32 %0, %%cluster_ctarank;" : "=r"(rank));
    const int cluster = blockIdx.x >> 3;
    const int b0 = cluster * 2;
    const int useg = (int)rank * 64;

    const int q = tid & 15;                   // u-quad (16 quads = 64 units)
    const int kb = tid >> 4;                  // k block (16 blocks of 32)
    const int ug = useg + q * 4;
    const int k0 = kb * 32;

    // R slice as k-pairs: Rp[j][i] = {R[k0+2i][ug+j], R[k0+2i+1][ug+j]}
    unsigned long long Rp[4][16];
#pragma unroll
    for (int i = 0; i < 16; i++) {
        float4 v0 = *reinterpret_cast<const float4*>(&R[(size_t)(k0 + 2 * i) * NU + ug]);
        float4 v1 = *reinterpret_cast<const float4*>(&R[(size_t)(k0 + 2 * i + 1) * NU + ug]);
        Rp[0][i] = pk2(v0.x, v1.x);
        Rp[1][i] = pk2(v0.y, v1.y);
        Rp[2][i] = pk2(v0.z, v1.z);
        Rp[3][i] = pk2(v0.w, v1.w);
    }

    // zero h_0 (parity-0 buffer)
    for (int i = tid; i < 8 * 2 * 64; i += 256) (&hbuf[0][0][0][0])[i] = 0.f;

    const uint32_t barL0 = (uint32_t)__cvta_generic_to_shared(&mbar[0]);
    const uint32_t barL1 = (uint32_t)__cvta_generic_to_shared(&mbar[1]);
    if (tid == 0) {
        asm volatile("mbarrier.init.shared.b64 [%0], 1;" :: "r"(barL0) : "memory");
        asm volatile("mbarrier.init.shared.b64 [%0], 1;" :: "r"(barL1) : "memory");
        // arm phase 0 of both (bar1 <- step-1 data, bar0 <- step-2 data)
        asm volatile("mbarrier.arrive.expect_tx.shared.b64 _, [%0], %1;"
                     :: "r"(barL0), "r"(4096) : "memory");
        asm volatile("mbarrier.arrive.expect_tx.shared.b64 _, [%0], %1;"
                     :: "r"(barL1), "r"(4096) : "memory");
    }
    __syncthreads();
    // one-time rendezvous: inits/arms + zeroed hbuf visible before any bulk
    asm volatile("barrier.cluster.arrive.aligned;" ::: "memory");
    asm volatile("barrier.cluster.wait.aligned;" ::: "memory");

    // owner threads (tid<128): one (batch, unit) output each
    const bool owner = tid < 128;
    const int ob = tid >> 6;
    const int ou = tid & 63;
    const int oq = ou >> 2, oj = ou & 3;
    const float* xwp = &g_xw[((size_t)(b0 + ob) * NT) * NU + useg + ou];
    float* outp = &out[((size_t)(b0 + ob) * NT) * NU + useg + ou];
    float xw_cur = owner ? xwp[0] : 0.f;

    // tid0-only: bulk-copy endpoint tables (per parity, per dest CTA)
    uint32_t dstA[2][8], mbarR[2][8], stageA[2];
    if (tid == 0) {
#pragma unroll
        for (int par = 0; par < 2; par++) {
            stageA[par] = (uint32_t)__cvta_generic_to_shared(&stage[par][0][0]);
            uint32_t slotL = (uint32_t)__cvta_generic_to_shared(&hbuf[par][rank][0][0]);
            uint32_t barL = par ? barL1 : barL0;
#pragma unroll
            for (int d = 0; d < 8; d++) {
                asm("mapa.shared::cluster.u32 %0, %1, %2;"
                    : "=r"(dstA[par][d]) : "r"(slotL), "r"(d));
                asm("mapa.shared::cluster.u32 %0, %1, %2;"
                    : "=r"(mbarR[par][d]) : "r"(barL), "r"(d));
            }
        }
    }

    uint32_t barAddr[2] = {barL0, barL1};
    int par[2] = {0, 0};

    for (int t = 0; t < NT; t++) {
        const int cur = t & 1;

        if (t > 0) {
            const int bsel = cur;  // data(t) tracked by mbar[t&1]
            const uint32_t ba = barAddr[bsel];
            const uint32_t ph = (uint32_t)par[bsel];
            uint32_t done;
            asm volatile(
                "{\n\t.reg .pred p;\n\t"
                "mbarrier.try_wait.parity.acquire.cluster.shared::cta.b64 p, [%1], %2;\n\t"
                "selp.b32 %0, 1, 0, p;\n\t}"
                : "=r"(done) : "r"(ba), "r"(ph) : "memory");
            while (!done) {
                asm volatile(
                    "{\n\t.reg .pred p;\n\t"
                    "mbarrier.try_wait.parity.acquire.cluster.shared::cta.b64 p, [%1], %2, 0x989680;\n\t"
                    "selp.b32 %0, 1, 0, p;\n\t}"
                    : "=r"(done) : "r"(ba), "r"(ph) : "memory");
            }
            par[bsel] ^= 1;
            // re-arm for step t+2: causal (peers' t+1 sends need my t sends,
            // which follow this re-arm in tid0's program order)
            if (tid == 0 && (t + 2) < NT) {
                asm volatile("mbarrier.arrive.expect_tx.shared.b64 _, [%0], %1;"
                             :: "r"(ba), "r"(4096) : "memory");
            }
        }

        // prefetch next xw (hidden under FMA loop)
        float xw_nxt = 0.f;
        if (owner && (t + 1) < NT) xw_nxt = xwp[(size_t)(t + 1) * NU];

        // ---- partial matvec over this thread's 32-k block, k-paired ----
        const float* h0 = &hbuf[cur][kb >> 1][0][(kb & 1) * 32];
        const float* h1 = &hbuf[cur][kb >> 1][1][(kb & 1) * 32];
        unsigned long long acc[2][4][2];
#pragma unroll
        for (int b = 0; b < 2; b++)
#pragma unroll
            for (int j = 0; j < 4; j++) { acc[b][j][0] = 0ull; acc[b][j][1] = 0ull; }

#pragma unroll
        for (int g = 0; g < 8; g++) {          // 8 groups of 4 k (= 2 k-pairs)
            ulonglong2 hp0 = *reinterpret_cast<const ulonglong2*>(&h0[g * 4]);
            ulonglong2 hp1 = *reinterpret_cast<const ulonglong2*>(&h1[g * 4]);
#pragma unroll
            for (int j = 0; j < 4; j++) {
                fma2(acc[0][j][0], Rp[j][2 * g + 0], hp0.x);
                fma2(acc[0][j][1], Rp[j][2 * g + 1], hp0.y);
                fma2(acc[1][j][0], Rp[j][2 * g + 0], hp1.x);
                fma2(acc[1][j][1], Rp[j][2 * g + 1], hp1.y);
            }
        }

        // ---- stash partials: horizontal-add pairs, conflict-free layout ----
#pragma unroll
        for (int b = 0; b < 2; b++)
#pragma unroll
            for (int j = 0; j < 4; j++) {
                float2 s0 = upk2(acc[b][j][0]);
                float2 s1 = upk2(acc[b][j][1]);
                red[kb][b][j][q] = (s0.x + s0.y) + (s1.x + s1.y);
            }
        __syncthreads();

        if (owner) {
            float s = 0.f;
#pragma unroll
            for (int r8 = 0; r8 < 16; r8++) s += red[r8][ob][oj][oq];
            const float val = xw_cur + s;
            outp[(size_t)t * NU] = val;

            const int p = cur ^ 1;            // parity of h_{t+1}
            stage[p][ob][ou] = val;           // local staging (parity double-buffered)

            // owners-only barrier: staging slice complete before bulk issue
            asm volatile("bar.sync 1, 128;" ::: "memory");

            // aggregated DSMEM push: 8 bulk copies, 512B each, one tx per dest
            // (never at the last step: no consumer; avoid async ops at teardown)
            if (tid == 0 && (t + 1) < NT) {
                asm volatile("fence.proxy.async.shared::cta;" ::: "memory");
#pragma unroll
                for (int d = 0; d < 8; d++) {
                    asm volatile(
                        "cp.async.bulk.shared::cluster.shared::cta.mbarrier::complete_tx::bytes "
                        "[%0], [%1], %2, [%3];"
                        :: "r"(dstA[p][d]), "r"(stageA[p]), "r"(512), "r"(mbarR[p][d])
                        : "memory");
                }
            }
        }
        xw_cur = xw_nxt;
    }

    // final rendezvous: no CTA exits while peers could still touch its smem
    asm volatile("barrier.cluster.arrive.aligned;" ::: "memory");
    asm volatile("barrier.cluster.wait.aligned;" ::: "memory");
}

// ======================================================================
extern "C" void kernel_launch(void* const* d_in, const int* in_sizes, int n_in,
                              void* d_out, int out_size) {
    const float* x = (const float*)d_in[0];            // [32,1024,512]
    const float* W = (const float*)d_in[1];            // kernel [512,512]
    const float* R = (const float*)d_in[2];            // recurrent_kernel [512,512]
    float* out = (float*)d_out;                        // [32,1024,512]

    dim3 gg(NU / 128, (NB * NT) / 128);                // (4, 256)
    xw_gemm<<<gg, 256>>>(x, W);
    scan_kernel<<<128, 256>>>(R, out);                 // 16 clusters x 8 CTAs
}